// round 2
// baseline (speedup 1.0000x reference)
#include <cuda_runtime.h>
#include <math.h>

#define KU 32

// ---------------- CG coefficients (computed on device, exact reference algo) ----------------
__device__ float g_cg[615];

__constant__ double C_fact[9] = {1.,1.,2.,6.,24.,120.,720.,5040.,40320.};

// 15 paths in (l3, path) order
__constant__ int I_l1[15]  = {0,1,2, 0,1,1,1,2,2, 0,1,1,2,2,2};
__constant__ int I_l2[15]  = {0,1,2, 1,0,1,2,1,2, 2,1,2,0,1,2};
__constant__ int I_l3[15]  = {0,0,0, 1,1,1,1,1,1, 2,2,2,2,2,2};
__constant__ int I_off[15] = {0,1,10, 35,44,53,80,125,170, 245,270,315,390,415,490};

// per-l3 path tables for the main kernel
__constant__ int C_np[3]     = {3,6,6};
__constant__ int C_d1[3][6]  = {{1,3,5,0,0,0},{1,3,3,3,5,5},{1,3,3,5,5,5}};
__constant__ int C_d2[3][6]  = {{1,3,5,0,0,0},{3,1,3,5,3,5},{5,3,5,1,3,5}};
__constant__ int C_xb[3][6]  = {{0,128,320,0,0,0},{0,128,128,128,320,320},{0,128,128,320,320,320}};
__constant__ int C_yo[3][6]  = {{0,1,4,0,0,0},{1,0,1,4,1,4},{4,1,4,0,1,4}};
__constant__ int C_cgo[3][6] = {{0,1,10,0,0,0},{35,44,53,80,125,170},{245,270,315,390,415,490}};
__constant__ int C_uo[3][6]  = {{0,128,192,0,0,0},{0,128,192,256,320,352},{0,128,192,256,288,320}};
__constant__ int C_ao[3][6]  = {{0,1,4,0,0,0},{0,3,12,21,30,45},{0,5,20,35,60,85}};

struct cplxd { double re, im; };
__device__ __forceinline__ cplxd cmul(cplxd a, cplxd b) {
    cplxd r; r.re = a.re*b.re - a.im*b.im; r.im = a.re*b.im + a.im*b.re; return r;
}

__device__ double su2_cg(int j1,int j2,int j3,int m1,int m2,int m3) {
    if (m3 != m1 + m2) return 0.0;
    double pref = sqrt((2.0*j3+1.0)*C_fact[j1+j2-j3]*C_fact[j1-j2+j3]*C_fact[-j1+j2+j3]
                       / C_fact[j1+j2+j3+1]);
    pref *= sqrt(C_fact[j3+m3]*C_fact[j3-m3]*C_fact[j1-m1]*C_fact[j1+m1]*C_fact[j2-m2]*C_fact[j2+m2]);
    double s = 0.0;
    for (int v = 0; v <= j1+j2-j3; v++) {
        int a = j1+j2-j3-v, b = j1-m1-v, c = j2+m2-v, d = j3-j2+m1+v, e = j3-j1-m2+v;
        if (a < 0 || b < 0 || c < 0 || d < 0 || e < 0) continue;
        double term = 1.0/(C_fact[v]*C_fact[a]*C_fact[b]*C_fact[c]*C_fact[d]*C_fact[e]);
        s += (v & 1) ? -term : term;
    }
    return pref * s;
}

// Q_l = (-i)^l * q_l, per reference _q(l). row/col in 0..2l.
__device__ cplxd Qe(int l, int row, int col) {
    const double RS2 = 0.70710678118654752440;
    cplxd q; q.re = 0.0; q.im = 0.0;
    int m = row - l;
    if (m < 0) {
        if (col == 2*l - row)      { q.re =  RS2; }
        else if (col == row)       { q.im = -RS2; }
    } else if (m == 0) {
        if (col == l)              { q.re = 1.0; }
    } else {
        double s = (m & 1) ? -1.0 : 1.0;
        if (col == row)            { q.re = s*RS2; }
        else if (col == 2*l - row) { q.im = s*RS2; }
    }
    if (l == 1)      { double t = q.re; q.re = q.im; q.im = -t; }   // * (-i)
    else if (l == 2) { q.re = -q.re; q.im = -q.im; }                // * (-1)
    return q;
}

// grid (15, 125), 32 threads: block (p, e) computes one real-CG coefficient
__global__ void cg_init_kernel() {
    int p = blockIdx.x, e = blockIdx.y;
    int l1 = I_l1[p], l2 = I_l2[p], l3 = I_l3[p];
    int d1 = 2*l1+1, d2 = 2*l2+1, d3 = 2*l3+1;
    if (e >= d1*d2*d3) return;
    int m = e % d3; int r = e / d3; int lc = r % d2; int j = r / d2;
    double acc = 0.0;
    for (int idx = threadIdx.x; idx < d1*d2; idx += 32) {
        int i = idx / d2, k = idx % d2;
        cplxd q1 = Qe(l1, i, j);  if (q1.re == 0.0 && q1.im == 0.0) continue;
        cplxd q2 = Qe(l2, k, lc); if (q2.re == 0.0 && q2.im == 0.0) continue;
        int m1 = i - l1, m2 = k - l2;
        int nn = l3 + m1 + m2;
        if (nn < 0 || nn >= d3) continue;
        cplxd q3 = Qe(l3, nn, m); q3.im = -q3.im;  // conj
        if (q3.re == 0.0 && q3.im == 0.0) continue;
        double cc = su2_cg(l1, l2, l3, m1, m2, m1 + m2);
        cplxd t = cmul(cmul(q1, q2), q3);
        acc += t.re * cc;
    }
    for (int o = 16; o; o >>= 1) acc += __shfl_down_sync(0xffffffffu, acc, o);
    if (threadIdx.x == 0) g_cg[I_off[p] + e] = (float)acc;
}

// ---------------- fused tensor-product + linear, one l3 per launch ----------------
// smem layout (floats): x[32*481] | y[32*9] | A[NA*36] | z[KU*D3*32] | W[KU*MULOUT] | cg[616] | ut[3*TOT]
__host__ __device__ constexpr int smem_floats(int D3, int MULOUT, int TOT, int NA) {
    return 32*481 + 32*9 + NA*36 + KU*D3*32 + KU*MULOUT + 616 + 3*TOT;
}

template<int L3, int D3, int MULOUT, int NV, int TOT, int NA, int OBASE>
__global__ void __launch_bounds__(256, 1)
tp_kernel(const float* __restrict__ x, const float* __restrict__ y,
          const float* __restrict__ W, float* __restrict__ out)
{
    constexpr int OFF_X  = 0;
    constexpr int OFF_Y  = OFF_X + 32*481;
    constexpr int OFF_A  = OFF_Y + 32*9;
    constexpr int OFF_Z  = OFF_A + NA*36;
    constexpr int OFF_W  = OFF_Z + KU*D3*32;
    constexpr int OFF_CG = OFF_W + KU*MULOUT;
    constexpr int OFF_UT = OFF_CG + 616;

    extern __shared__ float sm[];
    float* x_s  = sm + OFF_X;
    float* y_s  = sm + OFF_Y;
    float* A_s  = sm + OFF_A;
    float* z_s  = sm + OFF_Z;
    float* W_s  = sm + OFF_W;
    float* cg_s = sm + OFF_CG;
    int*   ut_x = (int*)(sm + OFF_UT);
    int*   ut_a = ut_x + TOT;
    int*   ut_d = ut_a + TOT;

    const int t  = threadIdx.x;
    const int b0 = blockIdx.x * 32;

    // stage CG table
    for (int i = t; i < 615; i += 256) cg_s[i] = g_cg[i];
    // build per-u tables
    for (int u = t; u < TOT; u += 256) {
        int p = C_np[L3] - 1;
        while (u < C_uo[L3][p]) p--;
        int mm = u - C_uo[L3][p];
        ut_x[u] = C_xb[L3][p] + mm * C_d1[L3][p];
        ut_a[u] = C_ao[L3][p];
        ut_d[u] = C_d1[L3][p];
    }
    // load x tile [b][481], y tile
    for (int i = t; i < 32*480; i += 256) {
        int b = i / 480, j = i - b*480;
        x_s[b*481 + j] = x[(size_t)(b0 + b)*480 + j];
    }
    for (int i = t; i < 32*9; i += 256) {
        int b = i / 9, j = i - b*9;
        y_s[b*9 + j] = y[(size_t)(b0 + b)*9 + j];
    }
    __syncthreads();

    // A phase: A_s[e][b] = sum_j CG[i,j,k] * y[b, yo+j], e=(path-rel i*D3+k)+ao
    for (int it = t; it < NA*32; it += 256) {
        int e = it >> 5, b = it & 31;
        int p = C_np[L3] - 1;
        while (e < C_ao[L3][p]) p--;
        int loc = e - C_ao[L3][p];
        int i = loc / D3, k = loc - i*D3;
        int d2 = C_d2[L3][p];
        const float* cg = &cg_s[C_cgo[L3][p] + (i*d2)*D3 + k];
        const float* yb = &y_s[b*9 + C_yo[L3][p]];
        float s = 0.f;
        for (int jj = 0; jj < d2; jj++) s += cg[jj*D3] * yb[jj];
        A_s[e*36 + b] = s;
    }
    __syncthreads();

    const int bgrp = t & 7;     // 8 groups of 4 batch rows
    const int vgrp = t >> 3;    // 32 v-groups of NV outputs
    float4 acc[NV][D3];
    #pragma unroll
    for (int n = 0; n < NV; n++)
        #pragma unroll
        for (int k = 0; k < D3; k++) acc[n][k] = make_float4(0.f,0.f,0.f,0.f);

    for (int uc = 0; uc < TOT; uc += KU) {
        // z phase: z_s[(ul*D3+k)][b] for 4-b quads
        for (int it = t; it < KU*D3*8; it += 256) {
            int bq = it & 7, e2 = it >> 3;
            int ul = e2 / D3, k = e2 - ul*D3;
            int u = uc + ul;
            int xo = ut_x[u], ao = ut_a[u], d1 = ut_d[u];
            float4 zz = make_float4(0.f,0.f,0.f,0.f);
            for (int i = 0; i < d1; i++) {
                float4 a4 = *(const float4*)&A_s[(ao + i*D3 + k)*36 + bq*4];
                const float* xr = &x_s[xo + i];
                zz.x += a4.x * xr[(bq*4+0)*481];
                zz.y += a4.y * xr[(bq*4+1)*481];
                zz.z += a4.z * xr[(bq*4+2)*481];
                zz.w += a4.w * xr[(bq*4+3)*481];
            }
            *(float4*)&z_s[e2*32 + bq*4] = zz;
        }
        // stage W chunk
        for (int i = t; i < KU*MULOUT/4; i += 256)
            ((float4*)W_s)[i] = ((const float4*)(W + (size_t)uc*MULOUT))[i];
        __syncthreads();

        // GEMM phase
        #pragma unroll 8
        for (int ul = 0; ul < KU; ul++) {
            float4 zv[D3];
            #pragma unroll
            for (int k = 0; k < D3; k++)
                zv[k] = *(const float4*)&z_s[(ul*D3 + k)*32 + bgrp*4];
            float wv[NV];
            if (NV == 4) {
                float4 w4 = *(const float4*)&W_s[ul*MULOUT + vgrp*4];
                wv[0] = w4.x; wv[1] = w4.y; wv[2] = w4.z; wv[3] = w4.w;
            } else {
                #pragma unroll
                for (int n = 0; n < NV; n++) wv[n] = W_s[ul*MULOUT + vgrp*NV + n];
            }
            #pragma unroll
            for (int n = 0; n < NV; n++)
                #pragma unroll
                for (int k = 0; k < D3; k++) {
                    acc[n][k].x += zv[k].x * wv[n];
                    acc[n][k].y += zv[k].y * wv[n];
                    acc[n][k].z += zv[k].z * wv[n];
                    acc[n][k].w += zv[k].w * wv[n];
                }
        }
        __syncthreads();
    }

    // stage output in smem (reuse x region), then coalesced store
    const float norm = rsqrtf((float)TOT);
    constexpr int S = MULOUT*D3 + 1;
    float* out_s = sm;
    #pragma unroll
    for (int n = 0; n < NV; n++)
        #pragma unroll
        for (int k = 0; k < D3; k++) {
            const float* av = (const float*)&acc[n][k];
            #pragma unroll
            for (int c = 0; c < 4; c++)
                out_s[(bgrp*4 + c)*S + (vgrp*NV + n)*D3 + k] = av[c] * norm;
        }
    __syncthreads();
    for (int i = t; i < 32*MULOUT*D3; i += 256) {
        int b = i / (MULOUT*D3), j = i - b*(MULOUT*D3);
        out[(size_t)(b0 + b)*480 + OBASE + j] = out_s[b*S + j];
    }
}

extern "C" void kernel_launch(void* const* d_in, const int* in_sizes, int n_in,
                              void* d_out, int out_size) {
    const float* x  = (const float*)d_in[0];
    const float* y  = (const float*)d_in[1];
    const float* W0 = (const float*)d_in[2];
    const float* W1 = (const float*)d_in[3];
    const float* W2 = (const float*)d_in[4];
    float* out = (float*)d_out;
    int B = in_sizes[0] / 480;
    int grid = B / 32;

    constexpr int S0 = smem_floats(1, 128, 224,   9) * 4;
    constexpr int S1 = smem_floats(3,  64, 384,  60) * 4;
    constexpr int S2 = smem_floats(5,  32, 352, 110) * 4;

    static bool attr_done = false;
    if (!attr_done) {
        cudaFuncSetAttribute((const void*)tp_kernel<0,1,128,4,224,9,0>,
                             cudaFuncAttributeMaxDynamicSharedMemorySize, S0);
        cudaFuncSetAttribute((const void*)tp_kernel<1,3,64,2,384,60,128>,
                             cudaFuncAttributeMaxDynamicSharedMemorySize, S1);
        cudaFuncSetAttribute((const void*)tp_kernel<2,5,32,1,352,110,320>,
                             cudaFuncAttributeMaxDynamicSharedMemorySize, S2);
        attr_done = true;
    }

    cg_init_kernel<<<dim3(15, 125), 32>>>();
    tp_kernel<0,1,128,4,224,9,0>   <<<grid, 256, S0>>>(x, y, W0, out);
    tp_kernel<1,3,64,2,384,60,128> <<<grid, 256, S1>>>(x, y, W1, out);
    tp_kernel<2,5,32,1,352,110,320><<<grid, 256, S2>>>(x, y, W2, out);
}

// round 3
// speedup vs baseline: 1.3621x; 1.3621x over previous
#include <cuda_runtime.h>
#include <math.h>

#define KU 32
#define XPITCH 68

// ---------------- CG coefficients (computed on device, exact reference algo) ----------------
__device__ float g_cg[615];

__constant__ double C_fact[9] = {1.,1.,2.,6.,24.,120.,720.,5040.,40320.};

// 15 paths in (l3, path) order
__constant__ int I_l1[15]  = {0,1,2, 0,1,1,1,2,2, 0,1,1,2,2,2};
__constant__ int I_l2[15]  = {0,1,2, 1,0,1,2,1,2, 2,1,2,0,1,2};
__constant__ int I_l3[15]  = {0,0,0, 1,1,1,1,1,1, 2,2,2,2,2,2};
__constant__ int I_off[15] = {0,1,10, 35,44,53,80,125,170, 245,270,315,390,415,490};

// per-l3 path tables
__constant__ int C_np[3]     = {3,6,6};
__constant__ int C_d1[3][6]  = {{1,3,5,0,0,0},{1,3,3,3,5,5},{1,3,3,5,5,5}};
__constant__ int C_d2[3][6]  = {{1,3,5,0,0,0},{3,1,3,5,3,5},{5,3,5,1,3,5}};
__constant__ int C_xb[3][6]  = {{0,128,320,0,0,0},{0,128,128,128,320,320},{0,128,128,320,320,320}};
__constant__ int C_yo[3][6]  = {{0,1,4,0,0,0},{1,0,1,4,1,4},{4,1,4,0,1,4}};
__constant__ int C_cgo[3][6] = {{0,1,10,0,0,0},{35,44,53,80,125,170},{245,270,315,390,415,490}};
__constant__ int C_uo[3][6]  = {{0,128,192,0,0,0},{0,128,192,256,320,352},{0,128,192,256,288,320}};
__constant__ int C_ao[3][6]  = {{0,1,4,0,0,0},{0,3,12,21,30,45},{0,5,20,35,60,85}};

struct cplxd { double re, im; };
__device__ __forceinline__ cplxd cmul(cplxd a, cplxd b) {
    cplxd r; r.re = a.re*b.re - a.im*b.im; r.im = a.re*b.im + a.im*b.re; return r;
}

__device__ double su2_cg(int j1,int j2,int j3,int m1,int m2,int m3) {
    if (m3 != m1 + m2) return 0.0;
    double pref = sqrt((2.0*j3+1.0)*C_fact[j1+j2-j3]*C_fact[j1-j2+j3]*C_fact[-j1+j2+j3]
                       / C_fact[j1+j2+j3+1]);
    pref *= sqrt(C_fact[j3+m3]*C_fact[j3-m3]*C_fact[j1-m1]*C_fact[j1+m1]*C_fact[j2-m2]*C_fact[j2+m2]);
    double s = 0.0;
    for (int v = 0; v <= j1+j2-j3; v++) {
        int a = j1+j2-j3-v, b = j1-m1-v, c = j2+m2-v, d = j3-j2+m1+v, e = j3-j1-m2+v;
        if (a < 0 || b < 0 || c < 0 || d < 0 || e < 0) continue;
        double term = 1.0/(C_fact[v]*C_fact[a]*C_fact[b]*C_fact[c]*C_fact[d]*C_fact[e]);
        s += (v & 1) ? -term : term;
    }
    return pref * s;
}

// Q_l = (-i)^l * q_l, per reference _q(l). row/col in 0..2l.
__device__ cplxd Qe(int l, int row, int col) {
    const double RS2 = 0.70710678118654752440;
    cplxd q; q.re = 0.0; q.im = 0.0;
    int m = row - l;
    if (m < 0) {
        if (col == 2*l - row)      { q.re =  RS2; }
        else if (col == row)       { q.im = -RS2; }
    } else if (m == 0) {
        if (col == l)              { q.re = 1.0; }
    } else {
        double s = (m & 1) ? -1.0 : 1.0;
        if (col == row)            { q.re = s*RS2; }
        else if (col == 2*l - row) { q.im = s*RS2; }
    }
    if (l == 1)      { double t = q.re; q.re = q.im; q.im = -t; }   // * (-i)
    else if (l == 2) { q.re = -q.re; q.im = -q.im; }                // * (-1)
    return q;
}

// grid (15, 125), 32 threads: block (p, e) computes one real-CG coefficient
__global__ void cg_init_kernel() {
    int p = blockIdx.x, e = blockIdx.y;
    int l1 = I_l1[p], l2 = I_l2[p], l3 = I_l3[p];
    int d1 = 2*l1+1, d2 = 2*l2+1, d3 = 2*l3+1;
    if (e >= d1*d2*d3) return;
    int m = e % d3; int r = e / d3; int lc = r % d2; int j = r / d2;
    double acc = 0.0;
    for (int idx = threadIdx.x; idx < d1*d2; idx += 32) {
        int i = idx / d2, k = idx % d2;
        cplxd q1 = Qe(l1, i, j);  if (q1.re == 0.0 && q1.im == 0.0) continue;
        cplxd q2 = Qe(l2, k, lc); if (q2.re == 0.0 && q2.im == 0.0) continue;
        int m1 = i - l1, m2 = k - l2;
        int nn = l3 + m1 + m2;
        if (nn < 0 || nn >= d3) continue;
        cplxd q3 = Qe(l3, nn, m); q3.im = -q3.im;  // conj
        if (q3.re == 0.0 && q3.im == 0.0) continue;
        double cc = su2_cg(l1, l2, l3, m1, m2, m1 + m2);
        cplxd t = cmul(cmul(q1, q2), q3);
        acc += t.re * cc;
    }
    for (int o = 16; o; o >>= 1) acc += __shfl_down_sync(0xffffffffu, acc, o);
    if (threadIdx.x == 0) g_cg[I_off[p] + e] = (float)acc;
}

// ---------------- fused tensor-product + linear ----------------
// smem (floats): xT[480*68] | y[64*9] | cg[616] | ut[3*TOT] | A[NA*64] | z[KU*D3*64] | W[KU*MULOUT]
template<int L3, int D3, int MULOUT, int NV, int TOT, int NA, int OBASE>
__device__ __forceinline__ void
tp_body(const float* __restrict__ x, const float* __restrict__ y,
        const float* __restrict__ W, float* __restrict__ out, float* sm)
{
    constexpr int OFF_XT = 0;
    constexpr int OFF_Y  = OFF_XT + 480*XPITCH;
    constexpr int OFF_CG = OFF_Y + 64*9;
    constexpr int OFF_UT = OFF_CG + 616;
    constexpr int OFF_A  = OFF_UT + 3*TOT;
    constexpr int OFF_Z  = OFF_A + NA*64;
    constexpr int OFF_W  = OFF_Z + KU*D3*64;

    float* xT  = sm + OFF_XT;
    float* y_s = sm + OFF_Y;
    float* cg_s= sm + OFF_CG;
    int*   ut_x= (int*)(sm + OFF_UT);
    int*   ut_a= ut_x + TOT;
    int*   ut_d= ut_a + TOT;
    float* A_s = sm + OFF_A;
    float* z_s = sm + OFF_Z;
    float* W_s = sm + OFF_W;

    const int t  = threadIdx.x;
    const int b0 = blockIdx.x * 64;

    // stage CG
    for (int i = t; i < 615; i += 256) cg_s[i] = g_cg[i];
    // per-u tables
    for (int u = t; u < TOT; u += 256) {
        int p = C_np[L3] - 1;
        while (u < C_uo[L3][p]) p--;
        int mm = u - C_uo[L3][p];
        ut_x[u] = C_xb[L3][p] + mm * C_d1[L3][p];
        ut_a[u] = C_ao[L3][p];
        ut_d[u] = C_d1[L3][p];
    }
    // y tile (contiguous)
    for (int i = t; i < 64*9; i += 256) y_s[i] = y[(size_t)b0*9 + i];
    // x tile transposed: xT[j*XPITCH + b]
    {
        const float4* x4 = (const float4*)(x + (size_t)b0*480);
        int warp = t >> 5, lane = t & 31;
        int bsub = lane >> 2, qi = lane & 3;
        for (int task = warp; task < 240; task += 8) {
            int bb = task & 7, qb = task >> 3;
            int b = bb*8 + bsub, q = qb*4 + qi;
            float4 v = x4[b*120 + q];
            float* dst = &xT[(4*q)*XPITCH + b];
            dst[0]        = v.x;
            dst[XPITCH]   = v.y;
            dst[2*XPITCH] = v.z;
            dst[3*XPITCH] = v.w;
        }
    }
    __syncthreads();

    // A phase: A_s[e*64 + b], e = ao(path) + i*D3 + k
    for (int it = t; it < NA*64; it += 256) {
        int e = it >> 6, b = it & 63;
        int p = C_np[L3] - 1;
        while (e < C_ao[L3][p]) p--;
        int loc = e - C_ao[L3][p];
        int i = loc / D3, k = loc - i*D3;
        int d2 = C_d2[L3][p];
        const float* cg = &cg_s[C_cgo[L3][p] + i*d2*D3 + k];
        const float* yb = &y_s[b*9 + C_yo[L3][p]];
        float s = 0.f;
        for (int jj = 0; jj < d2; jj++) s += cg[jj*D3] * yb[jj];
        A_s[e*64 + b] = s;
    }
    __syncthreads();

    const int bgrp = t & 15;    // 16 groups x 4 batch
    const int vgrp = t >> 4;    // 16 groups x NV outputs
    float4 acc[NV][D3];
    #pragma unroll
    for (int n = 0; n < NV; n++)
        #pragma unroll
        for (int k = 0; k < D3; k++) acc[n][k] = make_float4(0.f,0.f,0.f,0.f);

    for (int uc = 0; uc < TOT; uc += KU) {
        // z phase: items (ul, bq), 2 passes
        {
            int bq = t & 15, ul0 = t >> 4;
            #pragma unroll
            for (int pass = 0; pass < 2; pass++) {
                int ul = ul0 + pass*16;
                int u = uc + ul;
                int xo = ut_x[u], ao = ut_a[u], d1 = ut_d[u];
                float4 zz[D3];
                #pragma unroll
                for (int k = 0; k < D3; k++) zz[k] = make_float4(0.f,0.f,0.f,0.f);
                for (int i = 0; i < d1; i++) {
                    float4 xv = *(const float4*)&xT[(xo + i)*XPITCH + bq*4];
                    #pragma unroll
                    for (int k = 0; k < D3; k++) {
                        float4 a4 = *(const float4*)&A_s[(ao + i*D3 + k)*64 + bq*4];
                        zz[k].x += a4.x * xv.x;
                        zz[k].y += a4.y * xv.y;
                        zz[k].z += a4.z * xv.z;
                        zz[k].w += a4.w * xv.w;
                    }
                }
                #pragma unroll
                for (int k = 0; k < D3; k++)
                    *(float4*)&z_s[(ul*D3 + k)*64 + bq*4] = zz[k];
            }
        }
        // W chunk
        for (int i = t; i < KU*MULOUT/4; i += 256)
            ((float4*)W_s)[i] = ((const float4*)(W + (size_t)uc*MULOUT))[i];
        __syncthreads();

        // GEMM phase
        #pragma unroll 8
        for (int ul = 0; ul < KU; ul++) {
            float4 zv[D3];
            #pragma unroll
            for (int k = 0; k < D3; k++)
                zv[k] = *(const float4*)&z_s[(ul*D3 + k)*64 + bgrp*4];
            float wv[NV];
            if (NV == 2) {
                float2 w2 = *(const float2*)&W_s[ul*MULOUT + vgrp*2];
                wv[0] = w2.x; wv[1] = w2.y;
            } else if (NV == 4) {
                float4 w4 = *(const float4*)&W_s[ul*MULOUT + vgrp*4];
                wv[0] = w4.x; wv[1] = w4.y; wv[2] = w4.z; wv[3] = w4.w;
            } else {
                #pragma unroll
                for (int q = 0; q < NV/4; q++) {
                    float4 w4 = *(const float4*)&W_s[ul*MULOUT + vgrp*NV + q*4];
                    wv[q*4+0] = w4.x; wv[q*4+1] = w4.y; wv[q*4+2] = w4.z; wv[q*4+3] = w4.w;
                }
            }
            #pragma unroll
            for (int n = 0; n < NV; n++)
                #pragma unroll
                for (int k = 0; k < D3; k++) {
                    acc[n][k].x += zv[k].x * wv[n];
                    acc[n][k].y += zv[k].y * wv[n];
                    acc[n][k].z += zv[k].z * wv[n];
                    acc[n][k].w += zv[k].w * wv[n];
                }
        }
        __syncthreads();
    }

    // epilogue: stage in smem (reuse xT region), coalesced store
    const float norm = rsqrtf((float)TOT);
    constexpr int S = MULOUT*D3 + 1;
    float* out_s = sm;
    #pragma unroll
    for (int n = 0; n < NV; n++)
        #pragma unroll
        for (int k = 0; k < D3; k++) {
            int col = (vgrp*NV + n)*D3 + k;
            out_s[(bgrp*4 + 0)*S + col] = acc[n][k].x * norm;
            out_s[(bgrp*4 + 1)*S + col] = acc[n][k].y * norm;
            out_s[(bgrp*4 + 2)*S + col] = acc[n][k].z * norm;
            out_s[(bgrp*4 + 3)*S + col] = acc[n][k].w * norm;
        }
    __syncthreads();
    constexpr int MD3 = MULOUT*D3;
    for (int i = t; i < 64*MD3; i += 256) {
        int b = i / MD3, j = i - b*MD3;
        out[(size_t)(b0 + b)*480 + OBASE + j] = out_s[b*S + j];
    }
}

__global__ void __launch_bounds__(256, 1)
tp_fused(const float* __restrict__ x, const float* __restrict__ y,
         const float* __restrict__ W0, const float* __restrict__ W1,
         const float* __restrict__ W2, float* __restrict__ out)
{
    extern __shared__ float sm[];
    if (blockIdx.y == 0)      tp_body<0,1,128,8,224,  9,  0>(x, y, W0, out, sm);
    else if (blockIdx.y == 1) tp_body<1,3, 64,4,384, 60,128>(x, y, W1, out, sm);
    else                      tp_body<2,5, 32,2,352,110,320>(x, y, W2, out, sm);
}

extern "C" void kernel_launch(void* const* d_in, const int* in_sizes, int n_in,
                              void* d_out, int out_size) {
    const float* x  = (const float*)d_in[0];
    const float* y  = (const float*)d_in[1];
    const float* W0 = (const float*)d_in[2];
    const float* W1 = (const float*)d_in[3];
    const float* W2 = (const float*)d_in[4];
    float* out = (float*)d_out;
    int B = in_sizes[0] / 480;
    int grid = B / 64;

    // max smem over branches (l3=2): 480*68 + 576 + 616 + 3*352 + 110*64 + 32*5*64 + 32*32 floats
    constexpr int SMEM_BYTES = (480*XPITCH + 64*9 + 616 + 3*352 + 110*64 + KU*5*64 + KU*32) * 4;

    static bool attr_done = false;
    if (!attr_done) {
        cudaFuncSetAttribute((const void*)tp_fused,
                             cudaFuncAttributeMaxDynamicSharedMemorySize, SMEM_BYTES);
        attr_done = true;
    }

    cg_init_kernel<<<dim3(15, 125), 32>>>();
    tp_fused<<<dim3(grid, 3), 256, SMEM_BYTES>>>(x, y, W0, W1, W2, out);
}

// round 5
// speedup vs baseline: 1.4405x; 1.0576x over previous
#include <cuda_runtime.h>
#include <math.h>

#define KU 32
#define XPITCH 68

// ---------------- packed f32x2 helpers (sm_100+) ----------------
__device__ __forceinline__ unsigned long long ffma2(unsigned long long a,
                                                    unsigned long long b,
                                                    unsigned long long c) {
    unsigned long long d;
    asm("fma.rn.f32x2 %0, %1, %2, %3;" : "=l"(d) : "l"(a), "l"(b), "l"(c));
    return d;
}
__device__ __forceinline__ unsigned long long pack2(float lo, float hi) {
    unsigned long long r;
    asm("mov.b64 %0, {%1, %2};" : "=l"(r) : "f"(lo), "f"(hi));
    return r;
}
__device__ __forceinline__ void unpack2(unsigned long long v, float& lo, float& hi) {
    asm("mov.b64 {%0, %1}, %2;" : "=f"(lo), "=f"(hi) : "l"(v));
}

// ---------------- CG coefficients (computed on device, exact reference algo) ----------------
__device__ float g_cg[615];

__constant__ double C_fact[9] = {1.,1.,2.,6.,24.,120.,720.,5040.,40320.};

// 15 paths in (l3, path) order
__constant__ int I_l1[15]  = {0,1,2, 0,1,1,1,2,2, 0,1,1,2,2,2};
__constant__ int I_l2[15]  = {0,1,2, 1,0,1,2,1,2, 2,1,2,0,1,2};
__constant__ int I_l3[15]  = {0,0,0, 1,1,1,1,1,1, 2,2,2,2,2,2};
__constant__ int I_off[15] = {0,1,10, 35,44,53,80,125,170, 245,270,315,390,415,490};

// per-l3 path tables
__constant__ int C_np[3]     = {3,6,6};
__constant__ int C_d1[3][6]  = {{1,3,5,0,0,0},{1,3,3,3,5,5},{1,3,3,5,5,5}};
__constant__ int C_d2[3][6]  = {{1,3,5,0,0,0},{3,1,3,5,3,5},{5,3,5,1,3,5}};
__constant__ int C_xb[3][6]  = {{0,128,320,0,0,0},{0,128,128,128,320,320},{0,128,128,320,320,320}};
__constant__ int C_yo[3][6]  = {{0,1,4,0,0,0},{1,0,1,4,1,4},{4,1,4,0,1,4}};
__constant__ int C_cgo[3][6] = {{0,1,10,0,0,0},{35,44,53,80,125,170},{245,270,315,390,415,490}};
__constant__ int C_uo[3][6]  = {{0,128,192,0,0,0},{0,128,192,256,320,352},{0,128,192,256,288,320}};
__constant__ int C_ao[3][6]  = {{0,1,4,0,0,0},{0,3,12,21,30,45},{0,5,20,35,60,85}};

struct cplxd { double re, im; };
__device__ __forceinline__ cplxd cmul(cplxd a, cplxd b) {
    cplxd r; r.re = a.re*b.re - a.im*b.im; r.im = a.re*b.im + a.im*b.re; return r;
}

__device__ double su2_cg(int j1,int j2,int j3,int m1,int m2,int m3) {
    if (m3 != m1 + m2) return 0.0;
    double pref = sqrt((2.0*j3+1.0)*C_fact[j1+j2-j3]*C_fact[j1-j2+j3]*C_fact[-j1+j2+j3]
                       / C_fact[j1+j2+j3+1]);
    pref *= sqrt(C_fact[j3+m3]*C_fact[j3-m3]*C_fact[j1-m1]*C_fact[j1+m1]*C_fact[j2-m2]*C_fact[j2+m2]);
    double s = 0.0;
    for (int v = 0; v <= j1+j2-j3; v++) {
        int a = j1+j2-j3-v, b = j1-m1-v, c = j2+m2-v, d = j3-j2+m1+v, e = j3-j1-m2+v;
        if (a < 0 || b < 0 || c < 0 || d < 0 || e < 0) continue;
        double term = 1.0/(C_fact[v]*C_fact[a]*C_fact[b]*C_fact[c]*C_fact[d]*C_fact[e]);
        s += (v & 1) ? -term : term;
    }
    return pref * s;
}

// Q_l = (-i)^l * q_l, per reference _q(l). row/col in 0..2l.
__device__ cplxd Qe(int l, int row, int col) {
    const double RS2 = 0.70710678118654752440;
    cplxd q; q.re = 0.0; q.im = 0.0;
    int m = row - l;
    if (m < 0) {
        if (col == 2*l - row)      { q.re =  RS2; }
        else if (col == row)       { q.im = -RS2; }
    } else if (m == 0) {
        if (col == l)              { q.re = 1.0; }
    } else {
        double s = (m & 1) ? -1.0 : 1.0;
        if (col == row)            { q.re = s*RS2; }
        else if (col == 2*l - row) { q.im = s*RS2; }
    }
    if (l == 1)      { double t = q.re; q.re = q.im; q.im = -t; }   // * (-i)
    else if (l == 2) { q.re = -q.re; q.im = -q.im; }                // * (-1)
    return q;
}

// grid (15, 125), 32 threads
__global__ void cg_init_kernel() {
    int p = blockIdx.x, e = blockIdx.y;
    int l1 = I_l1[p], l2 = I_l2[p], l3 = I_l3[p];
    int d1 = 2*l1+1, d2 = 2*l2+1, d3 = 2*l3+1;
    if (e >= d1*d2*d3) return;
    int m = e % d3; int r = e / d3; int lc = r % d2; int j = r / d2;
    double acc = 0.0;
    for (int idx = threadIdx.x; idx < d1*d2; idx += 32) {
        int i = idx / d2, k = idx % d2;
        cplxd q1 = Qe(l1, i, j);  if (q1.re == 0.0 && q1.im == 0.0) continue;
        cplxd q2 = Qe(l2, k, lc); if (q2.re == 0.0 && q2.im == 0.0) continue;
        int m1 = i - l1, m2 = k - l2;
        int nn = l3 + m1 + m2;
        if (nn < 0 || nn >= d3) continue;
        cplxd q3 = Qe(l3, nn, m); q3.im = -q3.im;  // conj
        if (q3.re == 0.0 && q3.im == 0.0) continue;
        double cc = su2_cg(l1, l2, l3, m1, m2, m1 + m2);
        cplxd t = cmul(cmul(q1, q2), q3);
        acc += t.re * cc;
    }
    for (int o = 16; o; o >>= 1) acc += __shfl_down_sync(0xffffffffu, acc, o);
    if (threadIdx.x == 0) g_cg[I_off[p] + e] = (float)acc;
}

// ---------------- fused tensor-product + linear ----------------
// smem (floats): xT[480*68] | y[64*9] | cg[616] | ut[3*TOT] | A[NA*64] | z[KU*D3*64] | W[KU*MULOUT]
template<int L3, int D3, int MULOUT, int NV, int TOT, int NA, int OBASE, int BT>
__device__ __forceinline__ void
tp_body(const float* __restrict__ x, const float* __restrict__ y,
        const float* __restrict__ W, float* __restrict__ out, float* sm)
{
    constexpr int OFF_XT = 0;
    constexpr int OFF_Y  = OFF_XT + 480*XPITCH;
    constexpr int OFF_CG = OFF_Y + 64*9;
    constexpr int OFF_UT = OFF_CG + 616;
    constexpr int OFF_A  = OFF_UT + 3*TOT;
    constexpr int OFF_Z  = OFF_A + NA*64;
    constexpr int OFF_W  = OFF_Z + KU*D3*64;
    constexpr int BGR = 64 / BT;      // bgrp count
    constexpr int Q   = BT / 2;       // packed f32x2 units per thread-batch

    float* xT  = sm + OFF_XT;
    float* y_s = sm + OFF_Y;
    float* cg_s= sm + OFF_CG;
    int*   ut_x= (int*)(sm + OFF_UT);
    int*   ut_a= ut_x + TOT;
    int*   ut_d= ut_a + TOT;
    float* A_s = sm + OFF_A;
    float* z_s = sm + OFF_Z;
    float* W_s = sm + OFF_W;

    const int t  = threadIdx.x;
    const int b0 = blockIdx.x * 64;

    // stage CG
    for (int i = t; i < 615; i += 256) cg_s[i] = g_cg[i];
    // per-u tables
    for (int u = t; u < TOT; u += 256) {
        int p = C_np[L3] - 1;
        while (u < C_uo[L3][p]) p--;
        int mm = u - C_uo[L3][p];
        ut_x[u] = C_xb[L3][p] + mm * C_d1[L3][p];
        ut_a[u] = C_ao[L3][p];
        ut_d[u] = C_d1[L3][p];
    }
    // y tile
    for (int i = t; i < 64*9; i += 256) y_s[i] = y[(size_t)b0*9 + i];
    // x tile transposed: xT[j*XPITCH + b]
    {
        const float4* x4 = (const float4*)(x + (size_t)b0*480);
        int warp = t >> 5, lane = t & 31;
        int bsub = lane >> 2, qi = lane & 3;
        for (int task = warp; task < 240; task += 8) {
            int bb = task & 7, qb = task >> 3;
            int b = bb*8 + bsub, q = qb*4 + qi;
            float4 v = x4[b*120 + q];
            float* dst = &xT[(4*q)*XPITCH + b];
            dst[0]        = v.x;
            dst[XPITCH]   = v.y;
            dst[2*XPITCH] = v.z;
            dst[3*XPITCH] = v.w;
        }
    }
    __syncthreads();

    // A phase: A_s[e*64 + b]
    for (int it = t; it < NA*64; it += 256) {
        int e = it >> 6, b = it & 63;
        int p = C_np[L3] - 1;
        while (e < C_ao[L3][p]) p--;
        int loc = e - C_ao[L3][p];
        int i = loc / D3, k = loc - i*D3;
        int d2 = C_d2[L3][p];
        const float* cg = &cg_s[C_cgo[L3][p] + i*d2*D3 + k];
        const float* yb = &y_s[b*9 + C_yo[L3][p]];
        float s = 0.f;
        for (int jj = 0; jj < d2; jj++) s += cg[jj*D3] * yb[jj];
        A_s[e*64 + b] = s;
    }
    __syncthreads();

    const int bgrp = t & (BGR - 1);
    const int vgrp = t / BGR;
    unsigned long long acc[NV][D3][Q];
    #pragma unroll
    for (int n = 0; n < NV; n++)
        #pragma unroll
        for (int k = 0; k < D3; k++)
            #pragma unroll
            for (int q = 0; q < Q; q++) acc[n][k][q] = 0ULL;

    for (int uc = 0; uc < TOT; uc += KU) {
        // z phase (f32x2), items (ul, bq), 2 passes
        {
            int bq = t & 15, ul0 = t >> 4;
            #pragma unroll
            for (int pass = 0; pass < 2; pass++) {
                int ul = ul0 + pass*16;
                int u = uc + ul;
                int xo = ut_x[u], ao = ut_a[u], d1 = ut_d[u];
                ulonglong2 zz[D3];
                #pragma unroll
                for (int k = 0; k < D3; k++) { zz[k].x = 0ULL; zz[k].y = 0ULL; }
                for (int i = 0; i < d1; i++) {
                    ulonglong2 xv = *(const ulonglong2*)&xT[(xo + i)*XPITCH + bq*4];
                    #pragma unroll
                    for (int k = 0; k < D3; k++) {
                        ulonglong2 a2 = *(const ulonglong2*)&A_s[(ao + i*D3 + k)*64 + bq*4];
                        zz[k].x = ffma2(a2.x, xv.x, zz[k].x);
                        zz[k].y = ffma2(a2.y, xv.y, zz[k].y);
                    }
                }
                #pragma unroll
                for (int k = 0; k < D3; k++)
                    *(ulonglong2*)&z_s[(ul*D3 + k)*64 + bq*4] = zz[k];
            }
        }
        // W chunk
        for (int i = t; i < KU*MULOUT/4; i += 256)
            ((float4*)W_s)[i] = ((const float4*)(W + (size_t)uc*MULOUT))[i];
        __syncthreads();

        // GEMM phase (f32x2)
        #pragma unroll 4
        for (int ul = 0; ul < KU; ul++) {
            unsigned long long zv[D3][Q];
            #pragma unroll
            for (int k = 0; k < D3; k++) {
                const float* zp = &z_s[(ul*D3 + k)*64 + bgrp*BT];
                if (Q == 2) {
                    ulonglong2 v2 = *(const ulonglong2*)zp;
                    zv[k][0] = v2.x; zv[k][1] = v2.y;
                } else {
                    zv[k][0] = *(const unsigned long long*)zp;
                }
            }
            float wv[NV];
            #pragma unroll
            for (int nq = 0; nq < NV/4; nq++) {
                float4 w4 = *(const float4*)&W_s[ul*MULOUT + vgrp*NV + nq*4];
                wv[nq*4+0] = w4.x; wv[nq*4+1] = w4.y; wv[nq*4+2] = w4.z; wv[nq*4+3] = w4.w;
            }
            unsigned long long w2[NV];
            #pragma unroll
            for (int n = 0; n < NV; n++) w2[n] = pack2(wv[n], wv[n]);
            #pragma unroll
            for (int n = 0; n < NV; n++)
                #pragma unroll
                for (int k = 0; k < D3; k++)
                    #pragma unroll
                    for (int q = 0; q < Q; q++)
                        acc[n][k][q] = ffma2(zv[k][q], w2[n], acc[n][k][q]);
        }
        __syncthreads();
    }

    // epilogue: stage in smem (reuse xT region), coalesced store
    const float norm = rsqrtf((float)TOT);
    constexpr int S = MULOUT*D3 + 1;
    float* out_s = sm;
    #pragma unroll
    for (int n = 0; n < NV; n++)
        #pragma unroll
        for (int k = 0; k < D3; k++) {
            int col = (vgrp*NV + n)*D3 + k;
            #pragma unroll
            for (int q = 0; q < Q; q++) {
                float lo, hi;
                unpack2(acc[n][k][q], lo, hi);
                out_s[(bgrp*BT + 2*q + 0)*S + col] = lo * norm;
                out_s[(bgrp*BT + 2*q + 1)*S + col] = hi * norm;
            }
        }
    __syncthreads();
    constexpr int MD3 = MULOUT*D3;
    for (int i = t; i < 64*MD3; i += 256) {
        int b = i / MD3, j = i - b*MD3;
        out[(size_t)(b0 + b)*480 + OBASE + j] = out_s[b*S + j];
    }
}

__global__ void __launch_bounds__(256, 1)
tp_fused(const float* __restrict__ x, const float* __restrict__ y,
         const float* __restrict__ W0, const float* __restrict__ W1,
         const float* __restrict__ W2, float* __restrict__ out)
{
    extern __shared__ float sm[];
    if (blockIdx.y == 0)      tp_body<0,1,128,8,224,  9,  0,4>(x, y, W0, out, sm);
    else if (blockIdx.y == 1) tp_body<1,3, 64,4,384, 60,128,4>(x, y, W1, out, sm);
    else                      tp_body<2,5, 32,4,352,110,320,2>(x, y, W2, out, sm);
}

extern "C" void kernel_launch(void* const* d_in, const int* in_sizes, int n_in,
                              void* d_out, int out_size) {
    const float* x  = (const float*)d_in[0];
    const float* y  = (const float*)d_in[1];
    const float* W0 = (const float*)d_in[2];
    const float* W1 = (const float*)d_in[3];
    const float* W2 = (const float*)d_in[4];
    float* out = (float*)d_out;
    int B = in_sizes[0] / 480;
    int grid = B / 64;

    // max smem over branches (l3=2)
    constexpr int SMEM_BYTES = (480*XPITCH + 64*9 + 616 + 3*352 + 110*64 + KU*5*64 + KU*32) * 4;

    // unconditional: identical behavior on every call (capture-safe, deterministic)
    cudaFuncSetAttribute((const void*)tp_fused,
                         cudaFuncAttributeMaxDynamicSharedMemorySize, SMEM_BYTES);

    cg_init_kernel<<<dim3(15, 125), 32>>>();
    tp_fused<<<dim3(grid, 3), 256, SMEM_BYTES>>>(x, y, W0, W1, W2, out);
}

// round 6
// speedup vs baseline: 1.6067x; 1.1154x over previous
#include <cuda_runtime.h>
#include <math.h>

#define KU 32
#define BMAX 16384

// ---------------- packed f32x2 helpers (sm_100+) ----------------
__device__ __forceinline__ unsigned long long ffma2(unsigned long long a,
                                                    unsigned long long b,
                                                    unsigned long long c) {
    unsigned long long d;
    asm("fma.rn.f32x2 %0, %1, %2, %3;" : "=l"(d) : "l"(a), "l"(b), "l"(c));
    return d;
}
__device__ __forceinline__ unsigned long long pack2(float lo, float hi) {
    unsigned long long r;
    asm("mov.b64 %0, {%1, %2};" : "=l"(r) : "f"(lo), "f"(hi));
    return r;
}
__device__ __forceinline__ void unpack2(unsigned long long v, float& lo, float& hi) {
    asm("mov.b64 {%0, %1}, %2;" : "=f"(lo), "=f"(hi) : "l"(v));
}

// ---------------- global scratch: transposed x ----------------
__device__ float g_xT[480 * BMAX];   // [j][b]

// ---------------- CG coefficients (computed on device, exact reference algo) ----------------
__device__ float g_cg[615];

__constant__ double C_fact[9] = {1.,1.,2.,6.,24.,120.,720.,5040.,40320.};

// 15 paths in (l3, path) order
__constant__ int I_l1[15]  = {0,1,2, 0,1,1,1,2,2, 0,1,1,2,2,2};
__constant__ int I_l2[15]  = {0,1,2, 1,0,1,2,1,2, 2,1,2,0,1,2};
__constant__ int I_l3[15]  = {0,0,0, 1,1,1,1,1,1, 2,2,2,2,2,2};
__constant__ int I_off[15] = {0,1,10, 35,44,53,80,125,170, 245,270,315,390,415,490};

// per-l3 path tables
__constant__ int C_np[3]     = {3,6,6};
__constant__ int C_d1[3][6]  = {{1,3,5,0,0,0},{1,3,3,3,5,5},{1,3,3,5,5,5}};
__constant__ int C_d2[3][6]  = {{1,3,5,0,0,0},{3,1,3,5,3,5},{5,3,5,1,3,5}};
__constant__ int C_xb[3][6]  = {{0,128,320,0,0,0},{0,128,128,128,320,320},{0,128,128,320,320,320}};
__constant__ int C_yo[3][6]  = {{0,1,4,0,0,0},{1,0,1,4,1,4},{4,1,4,0,1,4}};
__constant__ int C_cgo[3][6] = {{0,1,10,0,0,0},{35,44,53,80,125,170},{245,270,315,390,415,490}};
__constant__ int C_uo[3][6]  = {{0,128,192,0,0,0},{0,128,192,256,320,352},{0,128,192,256,288,320}};
__constant__ int C_ao[3][6]  = {{0,1,4,0,0,0},{0,3,12,21,30,45},{0,5,20,35,60,85}};

struct cplxd { double re, im; };
__device__ __forceinline__ cplxd cmul(cplxd a, cplxd b) {
    cplxd r; r.re = a.re*b.re - a.im*b.im; r.im = a.re*b.im + a.im*b.re; return r;
}

__device__ double su2_cg(int j1,int j2,int j3,int m1,int m2,int m3) {
    if (m3 != m1 + m2) return 0.0;
    double pref = sqrt((2.0*j3+1.0)*C_fact[j1+j2-j3]*C_fact[j1-j2+j3]*C_fact[-j1+j2+j3]
                       / C_fact[j1+j2+j3+1]);
    pref *= sqrt(C_fact[j3+m3]*C_fact[j3-m3]*C_fact[j1-m1]*C_fact[j1+m1]*C_fact[j2-m2]*C_fact[j2+m2]);
    double s = 0.0;
    for (int v = 0; v <= j1+j2-j3; v++) {
        int a = j1+j2-j3-v, b = j1-m1-v, c = j2+m2-v, d = j3-j2+m1+v, e = j3-j1-m2+v;
        if (a < 0 || b < 0 || c < 0 || d < 0 || e < 0) continue;
        double term = 1.0/(C_fact[v]*C_fact[a]*C_fact[b]*C_fact[c]*C_fact[d]*C_fact[e]);
        s += (v & 1) ? -term : term;
    }
    return pref * s;
}

// Q_l = (-i)^l * q_l, per reference _q(l). row/col in 0..2l.
__device__ cplxd Qe(int l, int row, int col) {
    const double RS2 = 0.70710678118654752440;
    cplxd q; q.re = 0.0; q.im = 0.0;
    int m = row - l;
    if (m < 0) {
        if (col == 2*l - row)      { q.re =  RS2; }
        else if (col == row)       { q.im = -RS2; }
    } else if (m == 0) {
        if (col == l)              { q.re = 1.0; }
    } else {
        double s = (m & 1) ? -1.0 : 1.0;
        if (col == row)            { q.re = s*RS2; }
        else if (col == 2*l - row) { q.im = s*RS2; }
    }
    if (l == 1)      { double t = q.re; q.re = q.im; q.im = -t; }   // * (-i)
    else if (l == 2) { q.re = -q.re; q.im = -q.im; }                // * (-1)
    return q;
}

// grid (15, 125), 32 threads
__global__ void cg_init_kernel() {
    int p = blockIdx.x, e = blockIdx.y;
    int l1 = I_l1[p], l2 = I_l2[p], l3 = I_l3[p];
    int d1 = 2*l1+1, d2 = 2*l2+1, d3 = 2*l3+1;
    if (e >= d1*d2*d3) return;
    int m = e % d3; int r = e / d3; int lc = r % d2; int j = r / d2;
    double acc = 0.0;
    for (int idx = threadIdx.x; idx < d1*d2; idx += 32) {
        int i = idx / d2, k = idx % d2;
        cplxd q1 = Qe(l1, i, j);  if (q1.re == 0.0 && q1.im == 0.0) continue;
        cplxd q2 = Qe(l2, k, lc); if (q2.re == 0.0 && q2.im == 0.0) continue;
        int m1 = i - l1, m2 = k - l2;
        int nn = l3 + m1 + m2;
        if (nn < 0 || nn >= d3) continue;
        cplxd q3 = Qe(l3, nn, m); q3.im = -q3.im;  // conj
        if (q3.re == 0.0 && q3.im == 0.0) continue;
        double cc = su2_cg(l1, l2, l3, m1, m2, m1 + m2);
        cplxd t = cmul(cmul(q1, q2), q3);
        acc += t.re * cc;
    }
    for (int o = 16; o; o >>= 1) acc += __shfl_down_sync(0xffffffffu, acc, o);
    if (threadIdx.x == 0) g_cg[I_off[p] + e] = (float)acc;
}

// ---------------- x transpose: x[b][480] -> g_xT[j][b] ----------------
__global__ void __launch_bounds__(256, 4)
transpose_x(const float* __restrict__ x) {
    __shared__ float tile[32][33];
    int b0 = blockIdx.x * 32, j0 = blockIdx.y * 32;
    int tx = threadIdx.x & 31, ty = threadIdx.x >> 5;  // 32 x 8
    #pragma unroll
    for (int r = 0; r < 4; r++)
        tile[ty + 8*r][tx] = x[(size_t)(b0 + ty + 8*r)*480 + j0 + tx];
    __syncthreads();
    #pragma unroll
    for (int r = 0; r < 4; r++)
        g_xT[(size_t)(j0 + ty + 8*r)*BMAX + b0 + tx] = tile[tx][ty + 8*r];
}

// ---------------- fused tensor-product + linear ----------------
// smem (floats): y[64*9] | cg[616] | ut[3*TOT] | A[NA*64] | z[KU*D3*64] | W[KU*MULOUT]
template<int L3, int D3, int MULOUT, int NV, int TOT, int NA, int OBASE, int BT>
__device__ __forceinline__ void
tp_body(const float* __restrict__ y,
        const float* __restrict__ W, float* __restrict__ out, float* sm)
{
    constexpr int OFF_Y  = 0;
    constexpr int OFF_CG = OFF_Y + 64*9;
    constexpr int OFF_UT = OFF_CG + 616;
    constexpr int OFF_A  = OFF_UT + 3*TOT;
    constexpr int OFF_Z  = OFF_A + NA*64;
    constexpr int OFF_W  = OFF_Z + KU*D3*64;
    constexpr int BGR = 64 / BT;      // bgrp count
    constexpr int Q   = BT / 2;       // packed f32x2 units per thread-batch

    float* y_s = sm + OFF_Y;
    float* cg_s= sm + OFF_CG;
    int*   ut_x= (int*)(sm + OFF_UT);
    int*   ut_a= ut_x + TOT;
    int*   ut_d= ut_a + TOT;
    float* A_s = sm + OFF_A;
    float* z_s = sm + OFF_Z;
    float* W_s = sm + OFF_W;

    const int t  = threadIdx.x;
    const int b0 = blockIdx.x * 64;

    // stage CG
    for (int i = t; i < 615; i += 256) cg_s[i] = g_cg[i];
    // per-u tables
    for (int u = t; u < TOT; u += 256) {
        int p = C_np[L3] - 1;
        while (u < C_uo[L3][p]) p--;
        int mm = u - C_uo[L3][p];
        ut_x[u] = C_xb[L3][p] + mm * C_d1[L3][p];
        ut_a[u] = C_ao[L3][p];
        ut_d[u] = C_d1[L3][p];
    }
    // y tile
    for (int i = t; i < 64*9; i += 256) y_s[i] = y[(size_t)b0*9 + i];
    __syncthreads();

    // A phase: A_s[e*64 + b]
    for (int it = t; it < NA*64; it += 256) {
        int e = it >> 6, b = it & 63;
        int p = C_np[L3] - 1;
        while (e < C_ao[L3][p]) p--;
        int loc = e - C_ao[L3][p];
        int i = loc / D3, k = loc - i*D3;
        int d2 = C_d2[L3][p];
        const float* cg = &cg_s[C_cgo[L3][p] + i*d2*D3 + k];
        const float* yb = &y_s[b*9 + C_yo[L3][p]];
        float s = 0.f;
        for (int jj = 0; jj < d2; jj++) s += cg[jj*D3] * yb[jj];
        A_s[e*64 + b] = s;
    }
    __syncthreads();

    const int bgrp = t & (BGR - 1);
    const int vgrp = t / BGR;
    unsigned long long acc[NV][D3][Q];
    #pragma unroll
    for (int n = 0; n < NV; n++)
        #pragma unroll
        for (int k = 0; k < D3; k++)
            #pragma unroll
            for (int q = 0; q < Q; q++) acc[n][k][q] = 0ULL;

    for (int uc = 0; uc < TOT; uc += KU) {
        // z phase: items (ul, bq); x read from global transposed (coalesced, L2-hot)
        {
            int bq = t & 15, ul0 = t >> 4;
            #pragma unroll
            for (int pass = 0; pass < 2; pass++) {
                int ul = ul0 + pass*16;
                int u = uc + ul;
                int xo = ut_x[u], ao = ut_a[u], d1 = ut_d[u];
                // batch x loads for MLP
                ulonglong2 xv[5];
                for (int i = 0; i < d1; i++)
                    xv[i] = *(const ulonglong2*)&g_xT[(size_t)(xo + i)*BMAX + b0 + bq*4];
                ulonglong2 zz[D3];
                #pragma unroll
                for (int k = 0; k < D3; k++) { zz[k].x = 0ULL; zz[k].y = 0ULL; }
                for (int i = 0; i < d1; i++) {
                    #pragma unroll
                    for (int k = 0; k < D3; k++) {
                        ulonglong2 a2 = *(const ulonglong2*)&A_s[(ao + i*D3 + k)*64 + bq*4];
                        zz[k].x = ffma2(a2.x, xv[i].x, zz[k].x);
                        zz[k].y = ffma2(a2.y, xv[i].y, zz[k].y);
                    }
                }
                #pragma unroll
                for (int k = 0; k < D3; k++)
                    *(ulonglong2*)&z_s[(ul*D3 + k)*64 + bq*4] = zz[k];
            }
        }
        // W chunk
        for (int i = t; i < KU*MULOUT/4; i += 256)
            ((float4*)W_s)[i] = ((const float4*)(W + (size_t)uc*MULOUT))[i];
        __syncthreads();

        // GEMM phase (f32x2)
        #pragma unroll 2
        for (int ul = 0; ul < KU; ul++) {
            unsigned long long zv[D3][Q];
            #pragma unroll
            for (int k = 0; k < D3; k++) {
                const float* zp = &z_s[(ul*D3 + k)*64 + bgrp*BT];
                if (Q == 2) {
                    ulonglong2 v2 = *(const ulonglong2*)zp;
                    zv[k][0] = v2.x; zv[k][1] = v2.y;
                } else {
                    zv[k][0] = *(const unsigned long long*)zp;
                }
            }
            unsigned long long w2[NV];
            #pragma unroll
            for (int nq = 0; nq < NV/4; nq++) {
                float4 w4 = *(const float4*)&W_s[ul*MULOUT + vgrp*NV + nq*4];
                w2[nq*4+0] = pack2(w4.x, w4.x);
                w2[nq*4+1] = pack2(w4.y, w4.y);
                w2[nq*4+2] = pack2(w4.z, w4.z);
                w2[nq*4+3] = pack2(w4.w, w4.w);
            }
            #pragma unroll
            for (int n = 0; n < NV; n++)
                #pragma unroll
                for (int k = 0; k < D3; k++)
                    #pragma unroll
                    for (int q = 0; q < Q; q++)
                        acc[n][k][q] = ffma2(zv[k][q], w2[n], acc[n][k][q]);
        }
        __syncthreads();
    }

    // epilogue: stage in smem (reuse full buffer), coalesced store
    const float norm = rsqrtf((float)TOT);
    constexpr int S = MULOUT*D3 + 1;
    float* out_s = sm;
    #pragma unroll
    for (int n = 0; n < NV; n++)
        #pragma unroll
        for (int k = 0; k < D3; k++) {
            int col = (vgrp*NV + n)*D3 + k;
            #pragma unroll
            for (int q = 0; q < Q; q++) {
                float lo, hi;
                unpack2(acc[n][k][q], lo, hi);
                out_s[(bgrp*BT + 2*q + 0)*S + col] = lo * norm;
                out_s[(bgrp*BT + 2*q + 1)*S + col] = hi * norm;
            }
        }
    __syncthreads();
    constexpr int MD3 = MULOUT*D3;
    for (int i = t; i < 64*MD3; i += 256) {
        int b = i / MD3, j = i - b*MD3;
        out[(size_t)(b0 + b)*480 + OBASE + j] = out_s[b*S + j];
    }
}

__global__ void __launch_bounds__(256, 2)
tp_fused(const float* __restrict__ y,
         const float* __restrict__ W0, const float* __restrict__ W1,
         const float* __restrict__ W2, float* __restrict__ out)
{
    extern __shared__ float sm[];
    if (blockIdx.y == 0)      tp_body<0,1,128,8,224,  9,  0,4>(y, W0, out, sm);
    else if (blockIdx.y == 1) tp_body<1,3, 64,4,384, 60,128,4>(y, W1, out, sm);
    else                      tp_body<2,5, 32,4,352,110,320,2>(y, W2, out, sm);
}

extern "C" void kernel_launch(void* const* d_in, const int* in_sizes, int n_in,
                              void* d_out, int out_size) {
    const float* x  = (const float*)d_in[0];
    const float* y  = (const float*)d_in[1];
    const float* W0 = (const float*)d_in[2];
    const float* W1 = (const float*)d_in[3];
    const float* W2 = (const float*)d_in[4];
    float* out = (float*)d_out;
    int B = in_sizes[0] / 480;
    int grid = B / 64;

    // max smem over branches (l3=2): y+cg+ut+A+z+W
    constexpr int SMEM_BYTES = (64*9 + 616 + 3*352 + 110*64 + KU*5*64 + KU*32) * 4;

    cudaFuncSetAttribute((const void*)tp_fused,
                         cudaFuncAttributeMaxDynamicSharedMemorySize, SMEM_BYTES);

    cg_init_kernel<<<dim3(15, 125), 32>>>();
    transpose_x<<<dim3(B/32, 15), 256>>>(x);
    tp_fused<<<dim3(grid, 3), 256, SMEM_BYTES>>>(y, W0, W1, W2, out);
}

// round 7
// speedup vs baseline: 1.6486x; 1.0261x over previous
#include <cuda_runtime.h>
#include <math.h>

#define KU 16
#define BMAX 16384

// ---------------- packed f32x2 helpers (sm_100+) ----------------
__device__ __forceinline__ unsigned long long ffma2(unsigned long long a,
                                                    unsigned long long b,
                                                    unsigned long long c) {
    unsigned long long d;
    asm("fma.rn.f32x2 %0, %1, %2, %3;" : "=l"(d) : "l"(a), "l"(b), "l"(c));
    return d;
}
__device__ __forceinline__ unsigned long long pack2(float lo, float hi) {
    unsigned long long r;
    asm("mov.b64 %0, {%1, %2};" : "=l"(r) : "f"(lo), "f"(hi));
    return r;
}
__device__ __forceinline__ void unpack2(unsigned long long v, float& lo, float& hi) {
    asm("mov.b64 {%0, %1}, %2;" : "=f"(lo), "=f"(hi) : "l"(v));
}

// ---------------- global scratch: transposed x ----------------
__device__ float g_xT[480 * BMAX];   // [j][b]

// ---------------- CG coefficients (computed on HOST each call, copied in) ----------------
__device__ float g_cg[615];

// per-l3 path tables (device)
__constant__ int C_np[3]     = {3,6,6};
__constant__ int C_d1[3][6]  = {{1,3,5,0,0,0},{1,3,3,3,5,5},{1,3,3,5,5,5}};
__constant__ int C_d2[3][6]  = {{1,3,5,0,0,0},{3,1,3,5,3,5},{5,3,5,1,3,5}};
__constant__ int C_xb[3][6]  = {{0,128,320,0,0,0},{0,128,128,128,320,320},{0,128,128,320,320,320}};
__constant__ int C_yo[3][6]  = {{0,1,4,0,0,0},{1,0,1,4,1,4},{4,1,4,0,1,4}};
__constant__ int C_cgo[3][6] = {{0,1,10,0,0,0},{35,44,53,80,125,170},{245,270,315,390,415,490}};
__constant__ int C_uo[3][6]  = {{0,128,192,0,0,0},{0,128,192,256,320,352},{0,128,192,256,288,320}};
__constant__ int C_ao[3][6]  = {{0,1,4,0,0,0},{0,3,12,21,30,45},{0,5,20,35,60,85}};

// ================= host-side CG computation (exact reference algorithm) =================
namespace hostcg {
struct cpx { double re, im; };
static inline cpx cmul(cpx a, cpx b) { return { a.re*b.re - a.im*b.im, a.re*b.im + a.im*b.re }; }
static const double FACT[9] = {1.,1.,2.,6.,24.,120.,720.,5040.,40320.};

static double su2_cg(int j1,int j2,int j3,int m1,int m2,int m3) {
    if (m3 != m1 + m2) return 0.0;
    double pref = sqrt((2.0*j3+1.0)*FACT[j1+j2-j3]*FACT[j1-j2+j3]*FACT[-j1+j2+j3]
                       / FACT[j1+j2+j3+1]);
    pref *= sqrt(FACT[j3+m3]*FACT[j3-m3]*FACT[j1-m1]*FACT[j1+m1]*FACT[j2-m2]*FACT[j2+m2]);
    double s = 0.0;
    for (int v = 0; v <= j1+j2-j3; v++) {
        int a = j1+j2-j3-v, b = j1-m1-v, c = j2+m2-v, d = j3-j2+m1+v, e = j3-j1-m2+v;
        if (a < 0 || b < 0 || c < 0 || d < 0 || e < 0) continue;
        double term = 1.0/(FACT[v]*FACT[a]*FACT[b]*FACT[c]*FACT[d]*FACT[e]);
        s += (v & 1) ? -term : term;
    }
    return pref * s;
}

// Q_l = (-i)^l * q_l per reference _q(l); row/col in 0..2l
static cpx Qe(int l, int row, int col) {
    const double RS2 = 0.70710678118654752440;
    cpx q = {0.0, 0.0};
    int m = row - l;
    if (m < 0) {
        if (col == 2*l - row)      q.re =  RS2;
        else if (col == row)       q.im = -RS2;
    } else if (m == 0) {
        if (col == l)              q.re = 1.0;
    } else {
        double s = (m & 1) ? -1.0 : 1.0;
        if (col == row)            q.re = s*RS2;
        else if (col == 2*l - row) q.im = s*RS2;
    }
    if (l == 1)      { double t = q.re; q.re = q.im; q.im = -t; }   // * (-i)
    else if (l == 2) { q.re = -q.re; q.im = -q.im; }                // * (-1)
    return q;
}

static void compute(float* out615) {
    static const int PL1[15] = {0,1,2, 0,1,1,1,2,2, 0,1,1,2,2,2};
    static const int PL2[15] = {0,1,2, 1,0,1,2,1,2, 2,1,2,0,1,2};
    static const int PL3[15] = {0,0,0, 1,1,1,1,1,1, 2,2,2,2,2,2};
    static const int POFF[15]= {0,1,10, 35,44,53,80,125,170, 245,270,315,390,415,490};
    for (int p = 0; p < 15; p++) {
        int l1 = PL1[p], l2 = PL2[p], l3 = PL3[p];
        int d1 = 2*l1+1, d2 = 2*l2+1, d3 = 2*l3+1;
        for (int e = 0; e < d1*d2*d3; e++) {
            int m = e % d3; int r = e / d3; int lc = r % d2; int j = r / d2;
            double acc = 0.0;
            for (int i = 0; i < d1; i++) {
                cpx q1 = Qe(l1, i, j);
                if (q1.re == 0.0 && q1.im == 0.0) continue;
                for (int k = 0; k < d2; k++) {
                    cpx q2 = Qe(l2, k, lc);
                    if (q2.re == 0.0 && q2.im == 0.0) continue;
                    int m1 = i - l1, m2 = k - l2;
                    int nn = l3 + m1 + m2;
                    if (nn < 0 || nn >= d3) continue;
                    cpx q3 = Qe(l3, nn, m); q3.im = -q3.im;  // conj
                    if (q3.re == 0.0 && q3.im == 0.0) continue;
                    double cc = su2_cg(l1, l2, l3, m1, m2, m1 + m2);
                    cpx t = cmul(cmul(q1, q2), q3);
                    acc += t.re * cc;
                }
            }
            out615[POFF[p] + e] = (float)acc;
        }
    }
}
} // namespace hostcg

static float h_cg_buf[615];   // persistent host storage read by captured memcpy node

// ---------------- x transpose: x[b][480] -> g_xT[j][b] ----------------
__global__ void __launch_bounds__(256, 4)
transpose_x(const float* __restrict__ x) {
    __shared__ float tile[32][33];
    int b0 = blockIdx.x * 32, j0 = blockIdx.y * 32;
    int tx = threadIdx.x & 31, ty = threadIdx.x >> 5;  // 32 x 8
    #pragma unroll
    for (int r = 0; r < 4; r++)
        tile[ty + 8*r][tx] = x[(size_t)(b0 + ty + 8*r)*480 + j0 + tx];
    __syncthreads();
    #pragma unroll
    for (int r = 0; r < 4; r++)
        g_xT[(size_t)(j0 + ty + 8*r)*BMAX + b0 + tx] = tile[tx][ty + 8*r];
}

// ---------------- fused tensor-product + linear (double-buffered pipeline) ----------------
// smem (floats): y[64*9] | cg[616] | ut[3*TOT] | A[NA*64] | z[2][KU*D3*64] | W[2][KU*MULOUT]
template<int L3, int D3, int MULOUT, int NV, int TOT, int NA, int OBASE, int BT>
__device__ __forceinline__ void
tp_body(const float* __restrict__ y,
        const float* __restrict__ W, float* __restrict__ out, float* sm)
{
    constexpr int OFF_Y  = 0;
    constexpr int OFF_CG = OFF_Y + 64*9;
    constexpr int OFF_UT = OFF_CG + 616;
    constexpr int OFF_A  = OFF_UT + 3*TOT;
    constexpr int OFF_Z  = OFF_A + NA*64;
    constexpr int ZBUF   = KU*D3*64;
    constexpr int OFF_W  = OFF_Z + 2*ZBUF;
    constexpr int WBUF   = KU*MULOUT;
    constexpr int BGR = 64 / BT;
    constexpr int Q   = BT / 2;
    constexpr int NCH = TOT / KU;

    float* y_s = sm + OFF_Y;
    float* cg_s= sm + OFF_CG;
    int*   ut_x= (int*)(sm + OFF_UT);
    int*   ut_a= ut_x + TOT;
    int*   ut_d= ut_a + TOT;
    float* A_s = sm + OFF_A;
    float* z_s = sm + OFF_Z;
    float* W_s = sm + OFF_W;

    const int t  = threadIdx.x;
    const int b0 = blockIdx.x * 64;

    // stage CG
    for (int i = t; i < 615; i += 256) cg_s[i] = g_cg[i];
    // per-u tables
    for (int u = t; u < TOT; u += 256) {
        int p = C_np[L3] - 1;
        while (u < C_uo[L3][p]) p--;
        int mm = u - C_uo[L3][p];
        ut_x[u] = C_xb[L3][p] + mm * C_d1[L3][p];
        ut_a[u] = C_ao[L3][p];
        ut_d[u] = C_d1[L3][p];
    }
    // y tile
    for (int i = t; i < 64*9; i += 256) y_s[i] = y[(size_t)b0*9 + i];
    __syncthreads();

    // A phase: A_s[e*64 + b]
    for (int it = t; it < NA*64; it += 256) {
        int e = it >> 6, b = it & 63;
        int p = C_np[L3] - 1;
        while (e < C_ao[L3][p]) p--;
        int loc = e - C_ao[L3][p];
        int i = loc / D3, k = loc - i*D3;
        int d2 = C_d2[L3][p];
        const float* cg = &cg_s[C_cgo[L3][p] + i*d2*D3 + k];
        const float* yb = &y_s[b*9 + C_yo[L3][p]];
        float s = 0.f;
        for (int jj = 0; jj < d2; jj++) s += cg[jj*D3] * yb[jj];
        A_s[e*64 + b] = s;
    }
    __syncthreads();

    const int bgrp = t & (BGR - 1);
    const int vgrp = t / BGR;
    const int bq   = t & 15;       // producer lane: 16 x 4-batch quads
    const int ulp  = t >> 4;       // producer u-slot: 0..15 (== KU)

    unsigned long long acc[NV][D3][Q];
    #pragma unroll
    for (int n = 0; n < NV; n++)
        #pragma unroll
        for (int k = 0; k < D3; k++)
            #pragma unroll
            for (int q = 0; q < Q; q++) acc[n][k][q] = 0ULL;

    // -------- producer: fill z buf + W buf for chunk ch --------
    auto produce = [&](int ch, int buf) {
        int u = ch*KU + ulp;
        int xo = ut_x[u], ao = ut_a[u], d1 = ut_d[u];
        ulonglong2 xv[5];
        for (int i = 0; i < d1; i++)
            xv[i] = *(const ulonglong2*)&g_xT[(size_t)(xo + i)*BMAX + b0 + bq*4];
        ulonglong2 zz[D3];
        #pragma unroll
        for (int k = 0; k < D3; k++) { zz[k].x = 0ULL; zz[k].y = 0ULL; }
        for (int i = 0; i < d1; i++) {
            #pragma unroll
            for (int k = 0; k < D3; k++) {
                ulonglong2 a2 = *(const ulonglong2*)&A_s[(ao + i*D3 + k)*64 + bq*4];
                zz[k].x = ffma2(a2.x, xv[i].x, zz[k].x);
                zz[k].y = ffma2(a2.y, xv[i].y, zz[k].y);
            }
        }
        float* zb = z_s + buf*ZBUF;
        #pragma unroll
        for (int k = 0; k < D3; k++)
            *(ulonglong2*)&zb[(ulp*D3 + k)*64 + bq*4] = zz[k];
        float4* wb = (float4*)(W_s + buf*WBUF);
        const float4* wsrc = (const float4*)(W + (size_t)ch*KU*MULOUT);
        for (int i = t; i < KU*MULOUT/4; i += 256) wb[i] = wsrc[i];
    };

    produce(0, 0);
    __syncthreads();

    for (int ch = 0; ch < NCH; ch++) {
        int cur = ch & 1;
        if (ch + 1 < NCH) produce(ch + 1, cur ^ 1);

        const float* zb = z_s + cur*ZBUF;
        const float* wbs = W_s + cur*WBUF;
        #pragma unroll 4
        for (int ul = 0; ul < KU; ul++) {
            unsigned long long zv[D3][Q];
            #pragma unroll
            for (int k = 0; k < D3; k++) {
                const float* zp = &zb[(ul*D3 + k)*64 + bgrp*BT];
                if (Q == 2) {
                    ulonglong2 v2 = *(const ulonglong2*)zp;
                    zv[k][0] = v2.x; zv[k][1] = v2.y;
                } else {
                    zv[k][0] = *(const unsigned long long*)zp;
                }
            }
            unsigned long long w2[NV];
            #pragma unroll
            for (int nq = 0; nq < NV/4; nq++) {
                float4 w4 = *(const float4*)&wbs[ul*MULOUT + vgrp*NV + nq*4];
                w2[nq*4+0] = pack2(w4.x, w4.x);
                w2[nq*4+1] = pack2(w4.y, w4.y);
                w2[nq*4+2] = pack2(w4.z, w4.z);
                w2[nq*4+3] = pack2(w4.w, w4.w);
            }
            #pragma unroll
            for (int n = 0; n < NV; n++)
                #pragma unroll
                for (int k = 0; k < D3; k++)
                    #pragma unroll
                    for (int q = 0; q < Q; q++)
                        acc[n][k][q] = ffma2(zv[k][q], w2[n], acc[n][k][q]);
        }
        __syncthreads();
    }

    // epilogue: stage in smem (reuse), coalesced store
    const float norm = rsqrtf((float)TOT);
    constexpr int S = MULOUT*D3 + 1;
    float* out_s = sm;
    #pragma unroll
    for (int n = 0; n < NV; n++)
        #pragma unroll
        for (int k = 0; k < D3; k++) {
            int col = (vgrp*NV + n)*D3 + k;
            #pragma unroll
            for (int q = 0; q < Q; q++) {
                float lo, hi;
                unpack2(acc[n][k][q], lo, hi);
                out_s[(bgrp*BT + 2*q + 0)*S + col] = lo * norm;
                out_s[(bgrp*BT + 2*q + 1)*S + col] = hi * norm;
            }
        }
    __syncthreads();
    constexpr int MD3 = MULOUT*D3;
    for (int i = t; i < 64*MD3; i += 256) {
        int b = i / MD3, j = i - b*MD3;
        out[(size_t)(b0 + b)*480 + OBASE + j] = out_s[b*S + j];
    }
}

__global__ void __launch_bounds__(256, 2)
tp_fused(const float* __restrict__ y,
         const float* __restrict__ W0, const float* __restrict__ W1,
         const float* __restrict__ W2, float* __restrict__ out)
{
    extern __shared__ float sm[];
    if (blockIdx.y == 0)      tp_body<0,1,128,8,224,  9,  0,4>(y, W0, out, sm);
    else if (blockIdx.y == 1) tp_body<1,3, 64,4,384, 60,128,4>(y, W1, out, sm);
    else                      tp_body<2,5, 32,4,352,110,320,2>(y, W2, out, sm);
}

extern "C" void kernel_launch(void* const* d_in, const int* in_sizes, int n_in,
                              void* d_out, int out_size) {
    const float* x  = (const float*)d_in[0];
    const float* y  = (const float*)d_in[1];
    const float* W0 = (const float*)d_in[2];
    const float* W1 = (const float*)d_in[3];
    const float* W2 = (const float*)d_in[4];
    float* out = (float*)d_out;
    int B = in_sizes[0] / 480;
    int grid = B / 64;

    // CG coefficients on host (deterministic, same every call), async H2D (capture-legal)
    hostcg::compute(h_cg_buf);
    cudaMemcpyToSymbolAsync(g_cg, h_cg_buf, 615*sizeof(float), 0,
                            cudaMemcpyHostToDevice, 0);

    // max smem over branches (l3=2): y+cg+ut+A + 2*z + 2*W
    constexpr int SMEM_BYTES = (64*9 + 616 + 3*352 + 110*64 + 2*KU*5*64 + 2*KU*32) * 4;

    cudaFuncSetAttribute((const void*)tp_fused,
                         cudaFuncAttributeMaxDynamicSharedMemorySize, SMEM_BYTES);

    transpose_x<<<dim3(B/32, 15), 256>>>(x);
    tp_fused<<<dim3(grid, 3), 256, SMEM_BYTES>>>(y, W0, W1, W2, out);
}